// round 5
// baseline (speedup 1.0000x reference)
#include <cuda_runtime.h>
#include <cstdint>

#define BB 16
#define NN 1024
#define HH 768
#define NEG_INF_F (-9000000000000000.0f)
#define SLOPE_F 0.2f

#define MTILE 128
#define HCH 128
#define NHC (HH / HCH)                // 6
#define JT 64
#define NJT (NN / JT)                 // 16
#define TILE_F4 (JT * HCH / 4)        // 2048 float4 per buffer
#define GATHER_SMEM (2 * JT * HCH * 4)  // 65536 bytes

// ---- static device scratch (no allocations allowed) ----
__device__ uint32_t g_mask[(size_t)BB * NN * 32];   // adjacency bitmask, 2 MB
__device__ __align__(16) float g_u1[HH], g_u2[HH];
__device__ float g_s1p[NHC][BB * NN], g_s2p[NHC][BB * NN];
__device__ float g_s1[BB * NN], g_s2[BB * NN];

// ---------------------------------------------------------------------------
// prep_mask: adj (fp32 0/1) -> per-row bitmask (adj > 1e-6)
// ---------------------------------------------------------------------------
__global__ void prep_mask_kernel(const float* __restrict__ adj) {
    __shared__ unsigned char s_nib[256];
    const int row = blockIdx.x;
    const int t = threadIdx.x;
    const float4 v = ((const float4*)(adj + (size_t)row * NN))[t];
    unsigned nib = (v.x > 1e-6f ? 1u : 0u) | (v.y > 1e-6f ? 2u : 0u) |
                   (v.z > 1e-6f ? 4u : 0u) | (v.w > 1e-6f ? 8u : 0u);
    s_nib[t] = (unsigned char)nib;
    __syncthreads();
    if (t < 32) {
        uint32_t w = 0;
#pragma unroll
        for (int i = 0; i < 8; ++i) w |= ((uint32_t)s_nib[t * 8 + i]) << (4 * i);
        g_mask[(size_t)row * 32 + t] = w;
    }
}

// ---------------------------------------------------------------------------
// u1 = W @ a[:H], u2 = W @ a[H:]
// ---------------------------------------------------------------------------
__global__ void compute_u_kernel(const float* __restrict__ W, const float* __restrict__ a) {
    int g = blockIdx.x * blockDim.x + threadIdx.x;
    if (g >= HH) return;
    const float* wr = W + (size_t)g * HH;
    float u1 = 0.f, u2 = 0.f;
#pragma unroll 8
    for (int f = 0; f < HH; ++f) {
        float w = wr[f];
        u1 += w * a[f];
        u2 += w * a[HH + f];
    }
    g_u1[g] = u1;
    g_u2[g] = u2;
}

// ---------------------------------------------------------------------------
// gather + fused partial s1/s2.
// CTA: 128 rows x 128 h-cols. 512 threads; warp owns 8 rows, lane one float4.
// x staged via double-buffered 32 KB smem j-tiles (cp.async). 2 CTAs/SM.
// ---------------------------------------------------------------------------
__device__ __forceinline__ void cp_async16(uint32_t dst, const void* src) {
    asm volatile("cp.async.cg.shared.global [%0], [%1], 16;" :: "r"(dst), "l"(src) : "memory");
}
__device__ __forceinline__ uint32_t smem_u32(const void* p) {
    uint32_t a;
    asm("{ .reg .u64 t; cvta.to.shared.u64 t, %1; cvt.u32.u64 %0, t; }" : "=r"(a) : "l"(p));
    return a;
}

__device__ __forceinline__ void load_tile(uint32_t s_dst, const float* __restrict__ x,
                                          int b, int jt, int h0) {
    // tile = 64 rows x 32 float4; 512 threads -> 4 float4 each
    const float* src0 = x + ((size_t)b * NN + (size_t)jt * JT) * HH + h0;
    const int t = threadIdx.x;
#pragma unroll
    for (int i = 0; i < 4; ++i) {
        int f = t + i * 512;          // 0..2047
        int r = f >> 5;
        int c4 = f & 31;
        cp_async16(s_dst + (uint32_t)f * 16u, src0 + (size_t)r * HH + c4 * 4);
    }
    asm volatile("cp.async.commit_group;" ::: "memory");
}

__global__ void __launch_bounds__(512, 2) gather_kernel(const float* __restrict__ x,
                                                        float* __restrict__ nv) {
    extern __shared__ __align__(16) float xs[];     // [2][64][128]
    const uint32_t s_base = smem_u32(xs);

    const int mt = blockIdx.x;        // 0..7
    const int hc = blockIdx.y;        // 0..5
    const int b  = blockIdx.z;        // 0..15
    const int i0 = mt * MTILE;
    const int h0 = hc * HCH;

    const int wid = threadIdx.x >> 5;
    const int lane = threadIdx.x & 31;
    const int r0 = wid * 8;           // warp's first row within tile

    float4 acc[8];
#pragma unroll
    for (int r = 0; r < 8; ++r) acc[r] = make_float4(0.f, 0.f, 0.f, 0.f);

    const uint32_t* mbase = g_mask + ((size_t)(b * NN + i0 + r0)) * 32;

    load_tile(s_base, x, b, 0, h0);

    const float4* xs4 = (const float4*)xs;

    for (int jt = 0; jt < NJT; ++jt) {
        const int buf = jt & 1;
        if (jt + 1 < NJT) {
            load_tile(s_base + (uint32_t)(1 - buf) * (TILE_F4 * 16u), x, b, jt + 1, h0);
            asm volatile("cp.async.wait_group 1;" ::: "memory");
        } else {
            asm volatile("cp.async.wait_group 0;" ::: "memory");
        }
        __syncthreads();

        const float4* tb = xs4 + buf * TILE_F4;
        const int w0 = jt * 2;
#pragma unroll
        for (int r = 0; r < 8; ++r) {
            const uint32_t* mr = mbase + (size_t)r * 32 + w0;
            uint64_t m = (uint64_t)mr[0] | ((uint64_t)mr[1] << 32);
            float4 a = acc[r];
            // peel pairs for MLP on the LDS chain
            while (m) {
                int j0 = __ffsll((long long)m) - 1;
                m &= m - 1;
                if (m) {
                    int j1 = __ffsll((long long)m) - 1;
                    m &= m - 1;
                    float4 v0 = tb[(j0 << 5) + lane];
                    float4 v1 = tb[(j1 << 5) + lane];
                    a.x += v0.x + v1.x; a.y += v0.y + v1.y;
                    a.z += v0.z + v1.z; a.w += v0.w + v1.w;
                } else {
                    float4 v0 = tb[(j0 << 5) + lane];
                    a.x += v0.x; a.y += v0.y; a.z += v0.z; a.w += v0.w;
                }
            }
            acc[r] = a;
        }
        __syncthreads();
    }

    // writeout + fused partial dots with u1/u2
    const float4 w1 = ((const float4*)g_u1)[h0 / 4 + lane];
    const float4 w2 = ((const float4*)g_u2)[h0 / 4 + lane];
#pragma unroll
    for (int r = 0; r < 8; ++r) {
        const int gi = i0 + r0 + r;
        ((float4*)(nv + ((size_t)(b * NN + gi)) * HH + h0))[lane] = acc[r];
        float d1 = acc[r].x * w1.x + acc[r].y * w1.y + acc[r].z * w1.z + acc[r].w * w1.w;
        float d2 = acc[r].x * w2.x + acc[r].y * w2.y + acc[r].z * w2.z + acc[r].w * w2.w;
#pragma unroll
        for (int o = 16; o > 0; o >>= 1) {
            d1 += __shfl_down_sync(0xffffffffu, d1, o);
            d2 += __shfl_down_sync(0xffffffffu, d2, o);
        }
        if (lane == 0) {
            g_s1p[hc][b * NN + gi] = d1;
            g_s2p[hc][b * NN + gi] = d2;
        }
    }
}

// ---------------------------------------------------------------------------
// reduce partial s over the 6 h-chunks
// ---------------------------------------------------------------------------
__global__ void reduce_s_kernel() {
    const int row = blockIdx.x * 256 + threadIdx.x;
    float s1 = 0.f, s2 = 0.f;
#pragma unroll
    for (int c = 0; c < NHC; ++c) {
        s1 += g_s1p[c][row];
        s2 += g_s2p[c][row];
    }
    g_s1[row] = s1;
    g_s2[row] = s2;
}

// ---------------------------------------------------------------------------
// softmax: bitmask-driven, register-resident scores
// ---------------------------------------------------------------------------
__global__ void softmax_kernel(const float* __restrict__ nl, float* __restrict__ attn) {
    __shared__ float red[8];
    __shared__ float bc;
    const int row = blockIdx.x;
    const int b = row >> 10;
    const int tid = threadIdx.x;

    const float s1i = g_s1[row];
    const bool rv = nl[row] > 1e-6f;
    const uint32_t* mrow = g_mask + (size_t)row * 32;
    const float* nlb = nl + (size_t)b * NN;
    const float* s2b = g_s2 + (size_t)b * NN;

    float sc[4];
    float lmax = NEG_INF_F;
#pragma unroll
    for (int k = 0; k < 4; ++k) {
        const int j = tid + 256 * k;
        const uint32_t w = mrow[j >> 5];
        const bool v = (((w >> (j & 31)) & 1u) != 0u) && rv && (nlb[j] > 1e-6f);
        const float z = s1i + s2b[j];
        const float e = (z > 0.f) ? z : SLOPE_F * z;
        sc[k] = v ? e : NEG_INF_F;
        lmax = fmaxf(lmax, sc[k]);
    }
#pragma unroll
    for (int o = 16; o > 0; o >>= 1)
        lmax = fmaxf(lmax, __shfl_xor_sync(0xffffffffu, lmax, o));
    if ((tid & 31) == 0) red[tid >> 5] = lmax;
    __syncthreads();
    if (tid == 0) {
        float m = red[0];
#pragma unroll
        for (int k = 1; k < 8; ++k) m = fmaxf(m, red[k]);
        bc = m;
    }
    __syncthreads();
    const float m = bc;

    float lsum = 0.f;
#pragma unroll
    for (int k = 0; k < 4; ++k) {
        const float e = __expf(sc[k] - m);
        sc[k] = e;
        lsum += e;
    }
#pragma unroll
    for (int o = 16; o > 0; o >>= 1)
        lsum += __shfl_xor_sync(0xffffffffu, lsum, o);
    if ((tid & 31) == 0) red[tid >> 5] = lsum;
    __syncthreads();
    if (tid == 0) {
        float s = 0.f;
#pragma unroll
        for (int k = 0; k < 8; ++k) s += red[k];
        bc = 1.0f / s;
    }
    __syncthreads();
    const float inv = bc;

    float* orow = attn + (size_t)row * NN;
#pragma unroll
    for (int k = 0; k < 4; ++k)
        orow[tid + 256 * k] = sc[k] * inv;
}

// ---------------------------------------------------------------------------
extern "C" void kernel_launch(void* const* d_in, const int* in_sizes, int n_in,
                              void* d_out, int out_size) {
    const float* x   = (const float*)d_in[0];   // (B, N, H)
    const float* nl  = (const float*)d_in[1];   // (B, N)
    const float* adj = (const float*)d_in[2];   // (B, N, N)
    const float* W   = (const float*)d_in[3];   // (H, H)
    const float* a   = (const float*)d_in[4];   // (2H, 1)

    float* nv   = (float*)d_out;
    float* attn = nv + (size_t)BB * NN * HH;

    static int smem_set = 0;
    if (!smem_set) {
        cudaFuncSetAttribute(gather_kernel, cudaFuncAttributeMaxDynamicSharedMemorySize, GATHER_SMEM);
        smem_set = 1;
    }

    prep_mask_kernel<<<BB * NN, 256>>>(adj);
    compute_u_kernel<<<3, 256>>>(W, a);
    gather_kernel<<<dim3(NN / MTILE, NHC, BB), 512, GATHER_SMEM>>>(x, nv);
    reduce_s_kernel<<<BB * NN / 256, 256>>>();
    softmax_kernel<<<BB * NN, 256>>>(nl, attn);
}

// round 6
// speedup vs baseline: 1.2050x; 1.2050x over previous
#include <cuda_runtime.h>
#include <cuda_bf16.h>
#include <cstdint>

#define BB 16
#define NN 1024
#define HH 768
#define KK2 2048
#define NEG_INF_F (-9000000000000000.0f)
#define SLOPE_F 0.2f

// ---- static device scratch (no allocations allowed) ----
__device__ __align__(16) __nv_bfloat16 g_adjbf[(size_t)BB * NN * NN];  // 33.5 MB
__device__ __align__(16) __nv_bfloat16 g_xT[(size_t)BB * HH * KK2];    // 50.3 MB [b][h][kk]
__device__ uint32_t g_mask[(size_t)BB * NN * 32];                      // 2 MB
__device__ __align__(16) float g_u1[HH], g_u2[HH];
__device__ float g_s1[BB * NN], g_s2[BB * NN];

__device__ __forceinline__ uint32_t smem_u32(const void* p) {
    uint32_t a;
    asm("{ .reg .u64 t; cvta.to.shared.u64 t, %1; cvt.u32.u64 %0, t; }" : "=r"(a) : "l"(p));
    return a;
}
__device__ __forceinline__ void cp_async16(uint32_t dst, const void* src) {
    asm volatile("cp.async.cg.shared.global [%0], [%1], 16;" :: "r"(dst), "l"(src) : "memory");
}
__device__ __forceinline__ void ldmx4(uint32_t& r0, uint32_t& r1, uint32_t& r2, uint32_t& r3, uint32_t a) {
    asm volatile("ldmatrix.sync.aligned.m8n8.x4.shared.b16 {%0,%1,%2,%3}, [%4];"
                 : "=r"(r0), "=r"(r1), "=r"(r2), "=r"(r3) : "r"(a));
}
__device__ __forceinline__ void mma16816(float* d, const uint32_t* a, const uint32_t* b) {
    asm volatile("mma.sync.aligned.m16n8k16.row.col.f32.bf16.bf16.f32 "
                 "{%0,%1,%2,%3}, {%4,%5,%6,%7}, {%8,%9}, {%0,%1,%2,%3};"
                 : "+f"(d[0]), "+f"(d[1]), "+f"(d[2]), "+f"(d[3])
                 : "r"(a[0]), "r"(a[1]), "r"(a[2]), "r"(a[3]), "r"(b[0]), "r"(b[1]));
}

// ---------------------------------------------------------------------------
// prep_adj: fp32 -> bf16 (exact 0/1) + validity bitmask
// ---------------------------------------------------------------------------
__global__ void prep_adj_kernel(const float* __restrict__ adj) {
    __shared__ unsigned char s_nib[256];
    const int row = blockIdx.x;
    const int t = threadIdx.x;
    const float4 v = ((const float4*)(adj + (size_t)row * NN))[t];
    __nv_bfloat162 p0 = __floats2bfloat162_rn(v.x, v.y);
    __nv_bfloat162 p1 = __floats2bfloat162_rn(v.z, v.w);
    uint2 u;
    u.x = *(const uint32_t*)&p0;
    u.y = *(const uint32_t*)&p1;
    ((uint2*)(g_adjbf + (size_t)row * NN))[t] = u;
    unsigned nib = (v.x > 1e-6f ? 1u : 0u) | (v.y > 1e-6f ? 2u : 0u) |
                   (v.z > 1e-6f ? 4u : 0u) | (v.w > 1e-6f ? 8u : 0u);
    s_nib[t] = (unsigned char)nib;
    __syncthreads();
    if (t < 32) {
        uint32_t w = 0;
#pragma unroll
        for (int i = 0; i < 8; ++i) w |= ((uint32_t)s_nib[t * 8 + i]) << (4 * i);
        g_mask[(size_t)row * 32 + t] = w;
    }
}

// ---------------------------------------------------------------------------
// prep_x: transpose + hi/lo split -> xT[b][h][k]=hi, xT[b][h][1024+k]=lo
// ---------------------------------------------------------------------------
__global__ void prep_x_kernel(const float* __restrict__ x) {
    __shared__ float tile[32][33];
    const int b = blockIdx.z;
    const int k0 = blockIdx.y * 32;
    const int h0 = blockIdx.x * 32;
    const int tx = threadIdx.x, ty = threadIdx.y;
#pragma unroll
    for (int i = 0; i < 4; ++i) {
        int k = k0 + ty + i * 8;
        tile[ty + i * 8][tx] = x[((size_t)(b * NN + k)) * HH + h0 + tx];
    }
    __syncthreads();
#pragma unroll
    for (int i = 0; i < 4; ++i) {
        int h = h0 + ty + i * 8;
        int k = k0 + tx;
        float f = tile[tx][ty + i * 8];
        __nv_bfloat16 hi = __float2bfloat16(f);
        __nv_bfloat16 lo = __float2bfloat16(f - __bfloat162float(hi));
        size_t o = ((size_t)(b * HH + h)) * KK2 + k;
        g_xT[o] = hi;
        g_xT[o + NN] = lo;
    }
}

// ---------------------------------------------------------------------------
// u1 = W @ a[:H], u2 = W @ a[H:]
// ---------------------------------------------------------------------------
__global__ void compute_u_kernel(const float* __restrict__ W, const float* __restrict__ a) {
    int g = blockIdx.x * blockDim.x + threadIdx.x;
    if (g >= HH) return;
    const float* wr = W + (size_t)g * HH;
    float u1 = 0.f, u2 = 0.f;
#pragma unroll 8
    for (int f = 0; f < HH; ++f) {
        float w = wr[f];
        u1 += w * a[f];
        u2 += w * a[HH + f];
    }
    g_u1[g] = u1;
    g_u2[g] = u2;
}

// ---------------------------------------------------------------------------
// GEMM via mma.sync bf16: nv[b, i0:+128, h0:+128] = adj[b] @ (x_hi + x_lo)
// CTA 128x128, Ktile=64, double-buffered cp.async, XOR-swizzled smem.
// ---------------------------------------------------------------------------
#define KTILE 64
#define NKT (KK2 / KTILE)            // 32
#define STAGE_B 32768                // A 16KB + B 16KB
#define GEMM_SMEM (2 * STAGE_B)

__device__ __forceinline__ void gemm_load(uint32_t sbase, int stage,
                                          const __nv_bfloat16* gA,
                                          const __nv_bfloat16* gB, int kk0) {
    const int t = threadIdx.x;
    const uint32_t sA = sbase + (uint32_t)stage * STAGE_B;
    const uint32_t sB = sA + 16384u;
    const int k0A = kk0 & (NN - 1);
#pragma unroll
    for (int i = 0; i < 4; ++i) {
        int idx = t + i * 256;           // 0..1023
        int r = idx >> 3;                // row 0..127
        int c = idx & 7;                 // 16B chunk 0..7
        uint32_t soff = (uint32_t)(r * 128 + ((c ^ (r & 7)) * 16));
        cp_async16(sA + soff, gA + (size_t)r * NN + k0A + c * 8);
        cp_async16(sB + soff, gB + (size_t)r * KK2 + kk0 + c * 8);
    }
    asm volatile("cp.async.commit_group;" ::: "memory");
}

__global__ void __launch_bounds__(256, 2) gemm_kernel(float* __restrict__ nv) {
    extern __shared__ __align__(1024) char dsm[];
    const uint32_t sbase = smem_u32(dsm);
    const int tid = threadIdx.x;
    const int wid = tid >> 5, lane = tid & 31;
    const int warp_m = wid & 3, warp_n = wid >> 2;
    const int i0 = blockIdx.x * 128, h0 = blockIdx.y * 128;
    const int b = blockIdx.z;

    const __nv_bfloat16* gA0 = g_adjbf + ((size_t)(b * NN + i0)) * NN;
    const __nv_bfloat16* gB0 = g_xT + ((size_t)(b * HH + h0)) * KK2;

    float acc[2][8][4];
#pragma unroll
    for (int mi = 0; mi < 2; ++mi)
#pragma unroll
        for (int nf = 0; nf < 8; ++nf)
#pragma unroll
            for (int q = 0; q < 4; ++q) acc[mi][nf][q] = 0.f;

    const int rA = warp_m * 32 + (lane & 15);       // A ldmatrix row
    const int cselA = lane >> 4;
    const int rB0 = warp_n * 64 + (lane & 7) + ((lane >> 4) << 3);
    const int cselB = (lane >> 3) & 1;

    gemm_load(sbase, 0, gA0, gB0, 0);

#pragma unroll 1
    for (int kt = 0; kt < NKT; ++kt) {
        if (kt + 1 < NKT) {
            gemm_load(sbase, (kt + 1) & 1, gA0, gB0, (kt + 1) * KTILE);
            asm volatile("cp.async.wait_group 1;" ::: "memory");
        } else {
            asm volatile("cp.async.wait_group 0;" ::: "memory");
        }
        __syncthreads();

        const uint32_t sA = sbase + (uint32_t)(kt & 1) * STAGE_B;
        const uint32_t sB = sA + 16384u;
#pragma unroll
        for (int ks = 0; ks < 4; ++ks) {
            uint32_t a[2][4];
#pragma unroll
            for (int mi = 0; mi < 2; ++mi) {
                int row = rA + mi * 16;
                uint32_t ad = sA + (uint32_t)(row * 128 + (((ks * 2 + cselA) ^ (row & 7)) * 16));
                ldmx4(a[mi][0], a[mi][1], a[mi][2], a[mi][3], ad);
            }
            uint32_t bf[8][2];
#pragma unroll
            for (int nj = 0; nj < 4; ++nj) {
                int row = rB0 + nj * 16;
                uint32_t ad = sB + (uint32_t)(row * 128 + (((ks * 2 + cselB) ^ (row & 7)) * 16));
                uint32_t r0, r1, r2, r3;
                ldmx4(r0, r1, r2, r3, ad);
                bf[2 * nj][0] = r0; bf[2 * nj][1] = r1;
                bf[2 * nj + 1][0] = r2; bf[2 * nj + 1][1] = r3;
            }
#pragma unroll
            for (int mi = 0; mi < 2; ++mi)
#pragma unroll
                for (int nf = 0; nf < 8; ++nf)
                    mma16816(acc[mi][nf], a[mi], bf[nf]);
        }
        __syncthreads();
    }

    // epilogue
    const int g = lane >> 2, t4 = lane & 3;
#pragma unroll
    for (int mi = 0; mi < 2; ++mi) {
#pragma unroll
        for (int nf = 0; nf < 8; ++nf) {
            int row0 = i0 + warp_m * 32 + mi * 16 + g;
            int col = h0 + warp_n * 64 + nf * 8 + t4 * 2;
            float* p0 = nv + ((size_t)(b * NN) + row0) * HH + col;
            *(float2*)p0 = make_float2(acc[mi][nf][0], acc[mi][nf][1]);
            *(float2*)(p0 + 8 * HH) = make_float2(acc[mi][nf][2], acc[mi][nf][3]);
        }
    }
}

// ---------------------------------------------------------------------------
// s1/s2: one warp per row
// ---------------------------------------------------------------------------
__global__ void compute_s_kernel(const float* __restrict__ nv) {
    const int row = blockIdx.x * 8 + (threadIdx.x >> 5);
    const int lane = threadIdx.x & 31;
    const float4* r = (const float4*)(nv + (size_t)row * HH);
    const float4* u1 = (const float4*)g_u1;
    const float4* u2 = (const float4*)g_u2;
    float d1 = 0.f, d2 = 0.f;
#pragma unroll
    for (int k = lane; k < HH / 4; k += 32) {
        float4 v = r[k], w1 = u1[k], w2 = u2[k];
        d1 += v.x * w1.x + v.y * w1.y + v.z * w1.z + v.w * w1.w;
        d2 += v.x * w2.x + v.y * w2.y + v.z * w2.z + v.w * w2.w;
    }
#pragma unroll
    for (int o = 16; o > 0; o >>= 1) {
        d1 += __shfl_down_sync(0xffffffffu, d1, o);
        d2 += __shfl_down_sync(0xffffffffu, d2, o);
    }
    if (lane == 0) { g_s1[row] = d1; g_s2[row] = d2; }
}

// ---------------------------------------------------------------------------
// softmax: bitmask-driven, register-resident scores
// ---------------------------------------------------------------------------
__global__ void softmax_kernel(const float* __restrict__ nl, float* __restrict__ attn) {
    __shared__ float red[8];
    __shared__ float bc;
    const int row = blockIdx.x;
    const int b = row >> 10;
    const int tid = threadIdx.x;

    const float s1i = g_s1[row];
    const bool rv = nl[row] > 1e-6f;
    const uint32_t* mrow = g_mask + (size_t)row * 32;
    const float* nlb = nl + (size_t)b * NN;
    const float* s2b = g_s2 + (size_t)b * NN;

    float sc[4];
    float lmax = NEG_INF_F;
#pragma unroll
    for (int k = 0; k < 4; ++k) {
        const int j = tid + 256 * k;
        const uint32_t w = mrow[j >> 5];
        const bool v = (((w >> (j & 31)) & 1u) != 0u) && rv && (nlb[j] > 1e-6f);
        const float z = s1i + s2b[j];
        const float e = (z > 0.f) ? z : SLOPE_F * z;
        sc[k] = v ? e : NEG_INF_F;
        lmax = fmaxf(lmax, sc[k]);
    }
#pragma unroll
    for (int o = 16; o > 0; o >>= 1)
        lmax = fmaxf(lmax, __shfl_xor_sync(0xffffffffu, lmax, o));
    if ((tid & 31) == 0) red[tid >> 5] = lmax;
    __syncthreads();
    if (tid == 0) {
        float m = red[0];
#pragma unroll
        for (int k = 1; k < 8; ++k) m = fmaxf(m, red[k]);
        bc = m;
    }
    __syncthreads();
    const float m = bc;

    float lsum = 0.f;
#pragma unroll
    for (int k = 0; k < 4; ++k) {
        const float e = __expf(sc[k] - m);
        sc[k] = e;
        lsum += e;
    }
#pragma unroll
    for (int o = 16; o > 0; o >>= 1)
        lsum += __shfl_xor_sync(0xffffffffu, lsum, o);
    if ((tid & 31) == 0) red[tid >> 5] = lsum;
    __syncthreads();
    if (tid == 0) {
        float s = 0.f;
#pragma unroll
        for (int k = 0; k < 8; ++k) s += red[k];
        bc = 1.0f / s;
    }
    __syncthreads();
    const float inv = bc;

    float* orow = attn + (size_t)row * NN;
#pragma unroll
    for (int k = 0; k < 4; ++k)
        orow[tid + 256 * k] = sc[k] * inv;
}

// ---------------------------------------------------------------------------
extern "C" void kernel_launch(void* const* d_in, const int* in_sizes, int n_in,
                              void* d_out, int out_size) {
    const float* x   = (const float*)d_in[0];   // (B, N, H)
    const float* nl  = (const float*)d_in[1];   // (B, N)
    const float* adj = (const float*)d_in[2];   // (B, N, N)
    const float* W   = (const float*)d_in[3];   // (H, H)
    const float* a   = (const float*)d_in[4];   // (2H, 1)

    float* nv   = (float*)d_out;
    float* attn = nv + (size_t)BB * NN * HH;

    cudaFuncSetAttribute(gemm_kernel, cudaFuncAttributeMaxDynamicSharedMemorySize, GEMM_SMEM);

    prep_adj_kernel<<<BB * NN, 256>>>(adj);
    prep_x_kernel<<<dim3(HH / 32, NN / 32, BB), dim3(32, 8)>>>(x);
    compute_u_kernel<<<3, 256>>>(W, a);
    gemm_kernel<<<dim3(NN / 128, HH / 128, BB), 256, GEMM_SMEM>>>(nv);
    compute_s_kernel<<<(BB * NN) / 8, 256>>>(nv);
    softmax_kernel<<<BB * NN, 256>>>(nl, attn);
}

// round 8
// speedup vs baseline: 1.2691x; 1.0533x over previous
#include <cuda_runtime.h>
#include <cuda_bf16.h>
#include <cstdint>

#define BB 16
#define NN 1024
#define HH 768
#define KK2 2048
#define NEG_INF_F (-9000000000000000.0f)
#define SLOPE_F 0.2f
#define NSP 12   // s-partial slots: 6 h-chunks x 2 warp_n halves

// ---- static device scratch (no allocations allowed) ----
__device__ __align__(16) __nv_bfloat16 g_adjbf[(size_t)BB * NN * NN];  // 33.5 MB
__device__ __align__(16) __nv_bfloat16 g_xT[(size_t)BB * HH * KK2];    // 50.3 MB [b][h][kk]
__device__ uint32_t g_mask[(size_t)BB * NN * 32];                      // 2 MB
__device__ __align__(16) float g_u1[HH], g_u2[HH];
__device__ float g_s1p[NSP][BB * NN], g_s2p[NSP][BB * NN];
__device__ float g_s1[BB * NN], g_s2[BB * NN];

__device__ __forceinline__ uint32_t smem_u32(const void* p) {
    uint32_t a;
    asm("{ .reg .u64 t; cvta.to.shared.u64 t, %1; cvt.u32.u64 %0, t; }" : "=r"(a) : "l"(p));
    return a;
}
__device__ __forceinline__ void cp_async16(uint32_t dst, const void* src) {
    asm volatile("cp.async.cg.shared.global [%0], [%1], 16;" :: "r"(dst), "l"(src) : "memory");
}
__device__ __forceinline__ void ldmx4(uint32_t& r0, uint32_t& r1, uint32_t& r2, uint32_t& r3, uint32_t a) {
    asm volatile("ldmatrix.sync.aligned.m8n8.x4.shared.b16 {%0,%1,%2,%3}, [%4];"
                 : "=r"(r0), "=r"(r1), "=r"(r2), "=r"(r3) : "r"(a));
}
__device__ __forceinline__ void mma16816(float* d, const uint32_t* a, const uint32_t* b) {
    asm volatile("mma.sync.aligned.m16n8k16.row.col.f32.bf16.bf16.f32 "
                 "{%0,%1,%2,%3}, {%4,%5,%6,%7}, {%8,%9}, {%0,%1,%2,%3};"
                 : "+f"(d[0]), "+f"(d[1]), "+f"(d[2]), "+f"(d[3])
                 : "r"(a[0]), "r"(a[1]), "r"(a[2]), "r"(a[3]), "r"(b[0]), "r"(b[1]));
}

// ---------------------------------------------------------------------------
// prep_adj: fp32 -> bf16 (exact 0/1) + validity bitmask
// ---------------------------------------------------------------------------
__global__ void prep_adj_kernel(const float* __restrict__ adj) {
    __shared__ unsigned char s_nib[256];
    const int row = blockIdx.x;
    const int t = threadIdx.x;
    const float4 v = ((const float4*)(adj + (size_t)row * NN))[t];
    __nv_bfloat162 p0 = __floats2bfloat162_rn(v.x, v.y);
    __nv_bfloat162 p1 = __floats2bfloat162_rn(v.z, v.w);
    uint2 u;
    u.x = *(const uint32_t*)&p0;
    u.y = *(const uint32_t*)&p1;
    ((uint2*)(g_adjbf + (size_t)row * NN))[t] = u;
    unsigned nib = (v.x > 1e-6f ? 1u : 0u) | (v.y > 1e-6f ? 2u : 0u) |
                   (v.z > 1e-6f ? 4u : 0u) | (v.w > 1e-6f ? 8u : 0u);
    s_nib[t] = (unsigned char)nib;
    __syncthreads();
    if (t < 32) {
        uint32_t w = 0;
#pragma unroll
        for (int i = 0; i < 8; ++i) w |= ((uint32_t)s_nib[t * 8 + i]) << (4 * i);
        g_mask[(size_t)row * 32 + t] = w;
    }
}

// ---------------------------------------------------------------------------
// prep_x: transpose + hi/lo split, packed bf16x2 stores.
// ---------------------------------------------------------------------------
__global__ void prep_x_kernel(const float* __restrict__ x) {
    __shared__ float tile[64][33];
    const int b = blockIdx.z;
    const int k0 = blockIdx.y * 64;
    const int h0 = blockIdx.x * 32;
    const int t = threadIdx.x;
    const int wid = t >> 5, lane = t & 31;

#pragma unroll
    for (int i = 0; i < 8; ++i) {
        int r = wid + i * 8;
        tile[r][lane] = x[((size_t)(b * NN + k0 + r)) * HH + h0 + lane];
    }
    __syncthreads();

    uint32_t* xo = (uint32_t*)g_xT;
#pragma unroll
    for (int i = 0; i < 4; ++i) {
        const int h = h0 + wid + i * 8;
        const float f0 = tile[2 * lane][wid + i * 8];
        const float f1 = tile[2 * lane + 1][wid + i * 8];
        const __nv_bfloat16 h0b = __float2bfloat16(f0);
        const __nv_bfloat16 h1b = __float2bfloat16(f1);
        const __nv_bfloat16 l0b = __float2bfloat16(f0 - __bfloat162float(h0b));
        const __nv_bfloat16 l1b = __float2bfloat16(f1 - __bfloat162float(h1b));
        const uint32_t hi = (uint32_t)__bfloat16_as_ushort(h0b) | ((uint32_t)__bfloat16_as_ushort(h1b) << 16);
        const uint32_t lo = (uint32_t)__bfloat16_as_ushort(l0b) | ((uint32_t)__bfloat16_as_ushort(l1b) << 16);
        const size_t base = ((size_t)(b * HH + h)) * (KK2 / 2) + (k0 >> 1);
        xo[base + lane] = hi;
        xo[base + (NN >> 1) + lane] = lo;
    }
}

// ---------------------------------------------------------------------------
// u1 = W @ a[:H], u2 = W @ a[H:]
// ---------------------------------------------------------------------------
__global__ void compute_u_kernel(const float* __restrict__ W, const float* __restrict__ a) {
    int g = blockIdx.x * blockDim.x + threadIdx.x;
    if (g >= HH) return;
    const float* wr = W + (size_t)g * HH;
    float u1 = 0.f, u2 = 0.f;
#pragma unroll 8
    for (int f = 0; f < HH; ++f) {
        float w = wr[f];
        u1 += w * a[f];
        u2 += w * a[HH + f];
    }
    g_u1[g] = u1;
    g_u2[g] = u2;
}

// ---------------------------------------------------------------------------
// GEMM: A tile (adj) shared across hi/lo B halves. Stage = {A 16K, Bhi 16K, Blo 16K}.
// 2 stages (96 KB), NKT=16 K-iterations of 64, fused partial s1/s2 epilogue.
// ---------------------------------------------------------------------------
#define NKT 16
#define STAGE_B 49152
#define GEMM_SMEM (2 * STAGE_B)

__device__ __forceinline__ void gemm_load(uint32_t sbase, int stage,
                                          const __nv_bfloat16* gA,
                                          const __nv_bfloat16* gB, int kt) {
    const int t = threadIdx.x;
    const uint32_t sA = sbase + (uint32_t)stage * STAGE_B;
    const uint32_t sBh = sA + 16384u;
    const uint32_t sBl = sA + 32768u;
    const int k0 = kt * 64;
#pragma unroll
    for (int i = 0; i < 4; ++i) {
        int idx = t + i * 256;           // 0..1023
        int r = idx >> 3;                // row 0..127
        int c = idx & 7;                 // 16B chunk
        uint32_t soff = (uint32_t)(r * 128 + ((c ^ (r & 7)) * 16));
        cp_async16(sA + soff, gA + (size_t)r * NN + k0 + c * 8);
        cp_async16(sBh + soff, gB + (size_t)r * KK2 + k0 + c * 8);
        cp_async16(sBl + soff, gB + (size_t)r * KK2 + NN + k0 + c * 8);
    }
    asm volatile("cp.async.commit_group;" ::: "memory");
}

__global__ void __launch_bounds__(256, 2) gemm_kernel(float* __restrict__ nv) {
    extern __shared__ __align__(1024) char dsm[];
    const uint32_t sbase = smem_u32(dsm);
    const int tid = threadIdx.x;
    const int wid = tid >> 5, lane = tid & 31;
    const int warp_m = wid & 3, warp_n = wid >> 2;
    const int i0 = blockIdx.x * 128, h0 = blockIdx.y * 128;
    const int b = blockIdx.z;
    const int sp = blockIdx.y * 2 + warp_n;   // s-partial slot 0..11

    const __nv_bfloat16* gA0 = g_adjbf + ((size_t)(b * NN + i0)) * NN;
    const __nv_bfloat16* gB0 = g_xT + ((size_t)(b * HH + h0)) * KK2;

    float acc[2][8][4];
#pragma unroll
    for (int mi = 0; mi < 2; ++mi)
#pragma unroll
        for (int nf = 0; nf < 8; ++nf)
#pragma unroll
            for (int q = 0; q < 4; ++q) acc[mi][nf][q] = 0.f;

    const int rA = warp_m * 32 + (lane & 15);
    const int cselA = lane >> 4;
    const int rB0 = warp_n * 64 + (lane & 7) + ((lane >> 4) << 3);
    const int cselB = (lane >> 3) & 1;

    gemm_load(sbase, 0, gA0, gB0, 0);

#pragma unroll 1
    for (int kt = 0; kt < NKT; ++kt) {
        if (kt + 1 < NKT) {
            gemm_load(sbase, (kt + 1) & 1, gA0, gB0, kt + 1);
            asm volatile("cp.async.wait_group 1;" ::: "memory");
        } else {
            asm volatile("cp.async.wait_group 0;" ::: "memory");
        }
        __syncthreads();

        const uint32_t sA = sbase + (uint32_t)(kt & 1) * STAGE_B;
        const uint32_t sBh = sA + 16384u;
        const uint32_t sBl = sA + 32768u;
#pragma unroll
        for (int ks = 0; ks < 4; ++ks) {
            uint32_t a[2][4];
#pragma unroll
            for (int mi = 0; mi < 2; ++mi) {
                int row = rA + mi * 16;
                uint32_t ad = sA + (uint32_t)(row * 128 + (((ks * 2 + cselA) ^ (row & 7)) * 16));
                ldmx4(a[mi][0], a[mi][1], a[mi][2], a[mi][3], ad);
            }
            uint32_t bf[8][2];
#pragma unroll
            for (int nj = 0; nj < 4; ++nj) {
                int row = rB0 + nj * 16;
                uint32_t ad = sBh + (uint32_t)(row * 128 + (((ks * 2 + cselB) ^ (row & 7)) * 16));
                uint32_t r0, r1, r2, r3;
                ldmx4(r0, r1, r2, r3, ad);
                bf[2 * nj][0] = r0; bf[2 * nj][1] = r1;
                bf[2 * nj + 1][0] = r2; bf[2 * nj + 1][1] = r3;
            }
#pragma unroll
            for (int mi = 0; mi < 2; ++mi)
#pragma unroll
                for (int nf = 0; nf < 8; ++nf)
                    mma16816(acc[mi][nf], a[mi], bf[nf]);
#pragma unroll
            for (int nj = 0; nj < 4; ++nj) {
                int row = rB0 + nj * 16;
                uint32_t ad = sBl + (uint32_t)(row * 128 + (((ks * 2 + cselB) ^ (row & 7)) * 16));
                uint32_t r0, r1, r2, r3;
                ldmx4(r0, r1, r2, r3, ad);
                bf[2 * nj][0] = r0; bf[2 * nj][1] = r1;
                bf[2 * nj + 1][0] = r2; bf[2 * nj + 1][1] = r3;
            }
#pragma unroll
            for (int mi = 0; mi < 2; ++mi)
#pragma unroll
                for (int nf = 0; nf < 8; ++nf)
                    mma16816(acc[mi][nf], a[mi], bf[nf]);
        }
        __syncthreads();
    }

    // epilogue: store nv + fused partial s1/s2 (slot = hc*2 + warp_n)
    const int g = lane >> 2, t4 = lane & 3;
#pragma unroll
    for (int mi = 0; mi < 2; ++mi) {
        float d1a = 0.f, d1b = 0.f, d2a = 0.f, d2b = 0.f;
#pragma unroll
        for (int nf = 0; nf < 8; ++nf) {
            const int row0 = i0 + warp_m * 32 + mi * 16 + g;
            const int col = h0 + warp_n * 64 + nf * 8 + t4 * 2;
            float* p0 = nv + ((size_t)(b * NN) + row0) * HH + col;
            *(float2*)p0 = make_float2(acc[mi][nf][0], acc[mi][nf][1]);
            *(float2*)(p0 + 8 * HH) = make_float2(acc[mi][nf][2], acc[mi][nf][3]);
            const float u1c0 = g_u1[col], u1c1 = g_u1[col + 1];
            const float u2c0 = g_u2[col], u2c1 = g_u2[col + 1];
            d1a += acc[mi][nf][0] * u1c0 + acc[mi][nf][1] * u1c1;
            d1b += acc[mi][nf][2] * u1c0 + acc[mi][nf][3] * u1c1;
            d2a += acc[mi][nf][0] * u2c0 + acc[mi][nf][1] * u2c1;
            d2b += acc[mi][nf][2] * u2c0 + acc[mi][nf][3] * u2c1;
        }
#pragma unroll
        for (int o = 1; o <= 2; o <<= 1) {
            d1a += __shfl_xor_sync(0xffffffffu, d1a, o);
            d1b += __shfl_xor_sync(0xffffffffu, d1b, o);
            d2a += __shfl_xor_sync(0xffffffffu, d2a, o);
            d2b += __shfl_xor_sync(0xffffffffu, d2b, o);
        }
        if (t4 == 0) {
            const int row0 = b * NN + i0 + warp_m * 32 + mi * 16 + g;
            g_s1p[sp][row0] = d1a;
            g_s1p[sp][row0 + 8] = d1b;
            g_s2p[sp][row0] = d2a;
            g_s2p[sp][row0 + 8] = d2b;
        }
    }
}

// ---------------------------------------------------------------------------
// reduce partial s over the 12 slots
// ---------------------------------------------------------------------------
__global__ void reduce_s_kernel() {
    const int row = blockIdx.x * 256 + threadIdx.x;
    float s1 = 0.f, s2 = 0.f;
#pragma unroll
    for (int c = 0; c < NSP; ++c) {
        s1 += g_s1p[c][row];
        s2 += g_s2p[c][row];
    }
    g_s1[row] = s1;
    g_s2[row] = s2;
}

// ---------------------------------------------------------------------------
// softmax: bitmask-driven, register-resident scores
// ---------------------------------------------------------------------------
__global__ void softmax_kernel(const float* __restrict__ nl, float* __restrict__ attn) {
    __shared__ float red[8];
    __shared__ float bc;
    const int row = blockIdx.x;
    const int b = row >> 10;
    const int tid = threadIdx.x;

    const float s1i = g_s1[row];
    const bool rv = nl[row] > 1e-6f;
    const uint32_t* mrow = g_mask + (size_t)row * 32;
    const float* nlb = nl + (size_t)b * NN;
    const float* s2b = g_s2 + (size_t)b * NN;

    float sc[4];
    float lmax = NEG_INF_F;
#pragma unroll
    for (int k = 0; k < 4; ++k) {
        const int j = tid + 256 * k;
        const uint32_t w = mrow[j >> 5];
        const bool v = (((w >> (j & 31)) & 1u) != 0u) && rv && (nlb[j] > 1e-6f);
        const float z = s1i + s2b[j];
        const float e = (z > 0.f) ? z : SLOPE_F * z;
        sc[k] = v ? e : NEG_INF_F;
        lmax = fmaxf(lmax, sc[k]);
    }
#pragma unroll
    for (int o = 16; o > 0; o >>= 1)
        lmax = fmaxf(lmax, __shfl_xor_sync(0xffffffffu, lmax, o));
    if ((tid & 31) == 0) red[tid >> 5] = lmax;
    __syncthreads();
    if (tid == 0) {
        float m = red[0];
#pragma unroll
        for (int k = 1; k < 8; ++k) m = fmaxf(m, red[k]);
        bc = m;
    }
    __syncthreads();
    const float m = bc;

    float lsum = 0.f;
#pragma unroll
    for (int k = 0; k < 4; ++k) {
        const float e = __expf(sc[k] - m);
        sc[k] = e;
        lsum += e;
    }
#pragma unroll
    for (int o = 16; o > 0; o >>= 1)
        lsum += __shfl_xor_sync(0xffffffffu, lsum, o);
    if ((tid & 31) == 0) red[tid >> 5] = lsum;
    __syncthreads();
    if (tid == 0) {
        float s = 0.f;
#pragma unroll
        for (int k = 0; k < 8; ++k) s += red[k];
        bc = 1.0f / s;
    }
    __syncthreads();
    const float inv = bc;

    float* orow = attn + (size_t)row * NN;
#pragma unroll
    for (int k = 0; k < 4; ++k)
        orow[tid + 256 * k] = sc[k] * inv;
}

// ---------------------------------------------------------------------------
extern "C" void kernel_launch(void* const* d_in, const int* in_sizes, int n_in,
                              void* d_out, int out_size) {
    const float* x   = (const float*)d_in[0];   // (B, N, H)
    const float* nl  = (const float*)d_in[1];   // (B, N)
    const float* adj = (const float*)d_in[2];   // (B, N, N)
    const float* W   = (const float*)d_in[3];   // (H, H)
    const float* a   = (const float*)d_in[4];   // (2H, 1)

    float* nv   = (float*)d_out;
    float* attn = nv + (size_t)BB * NN * HH;

    cudaFuncSetAttribute(gemm_kernel, cudaFuncAttributeMaxDynamicSharedMemorySize, GEMM_SMEM);

    prep_adj_kernel<<<BB * NN, 256>>>(adj);
    prep_x_kernel<<<dim3(HH / 32, NN / 64, BB), 256>>>(x);
    compute_u_kernel<<<3, 256>>>(W, a);
    gemm_kernel<<<dim3(NN / 128, HH / 128, BB), 256, GEMM_SMEM>>>(nv);
    reduce_s_kernel<<<BB * NN / 256, 256>>>();
    softmax_kernel<<<BB * NN, 256>>>(nl, attn);
}

// round 9
// speedup vs baseline: 1.4292x; 1.1261x over previous
#include <cuda_runtime.h>
#include <cuda_fp16.h>
#include <cstdint>

#define BB 16
#define NN 1024
#define HH 768
#define NEG_INF_F (-9000000000000000.0f)
#define SLOPE_F 0.2f

// ---- static device scratch (no allocations allowed) ----
__device__ __align__(16) __half g_adjh[(size_t)BB * NN * NN];   // adj fp16 (exact 0/1) 33.5 MB
__device__ __align__(16) __half g_xT[(size_t)BB * HH * NN];     // xT fp16 [b][h][k] 25 MB
__device__ uint32_t g_mask[(size_t)BB * NN * 32];               // 2 MB
__device__ __align__(16) float g_u1[HH], g_u2[HH];
__device__ float g_v1[BB * NN], g_v2[BB * NN];
__device__ float g_s1[BB * NN], g_s2[BB * NN];

__device__ __forceinline__ uint32_t smem_u32(const void* p) {
    uint32_t a;
    asm("{ .reg .u64 t; cvta.to.shared.u64 t, %1; cvt.u32.u64 %0, t; }" : "=r"(a) : "l"(p));
    return a;
}
__device__ __forceinline__ void cp_async16(uint32_t dst, const void* src) {
    asm volatile("cp.async.cg.shared.global [%0], [%1], 16;" :: "r"(dst), "l"(src) : "memory");
}
__device__ __forceinline__ void ldmx4(uint32_t& r0, uint32_t& r1, uint32_t& r2, uint32_t& r3, uint32_t a) {
    asm volatile("ldmatrix.sync.aligned.m8n8.x4.shared.b16 {%0,%1,%2,%3}, [%4];"
                 : "=r"(r0), "=r"(r1), "=r"(r2), "=r"(r3) : "r"(a));
}
__device__ __forceinline__ void mma16816(float* d, const uint32_t* a, const uint32_t* b) {
    asm volatile("mma.sync.aligned.m16n8k16.row.col.f32.f16.f16.f32 "
                 "{%0,%1,%2,%3}, {%4,%5,%6,%7}, {%8,%9}, {%0,%1,%2,%3};"
                 : "+f"(d[0]), "+f"(d[1]), "+f"(d[2]), "+f"(d[3])
                 : "r"(a[0]), "r"(a[1]), "r"(a[2]), "r"(a[3]), "r"(b[0]), "r"(b[1]));
}

// ---------------------------------------------------------------------------
// prep_adj: fp32 -> fp16 (exact 0/1) + validity bitmask
// ---------------------------------------------------------------------------
__global__ void prep_adj_kernel(const float* __restrict__ adj) {
    __shared__ unsigned char s_nib[256];
    const int row = blockIdx.x;
    const int t = threadIdx.x;
    const float4 v = ((const float4*)(adj + (size_t)row * NN))[t];
    __half2 p0 = __floats2half2_rn(v.x, v.y);
    __half2 p1 = __floats2half2_rn(v.z, v.w);
    uint2 u;
    u.x = *(const uint32_t*)&p0;
    u.y = *(const uint32_t*)&p1;
    ((uint2*)(g_adjh + (size_t)row * NN))[t] = u;
    unsigned nib = (v.x > 1e-6f ? 1u : 0u) | (v.y > 1e-6f ? 2u : 0u) |
                   (v.z > 1e-6f ? 4u : 0u) | (v.w > 1e-6f ? 8u : 0u);
    s_nib[t] = (unsigned char)nib;
    __syncthreads();
    if (t < 32) {
        uint32_t w = 0;
#pragma unroll
        for (int i = 0; i < 8; ++i) w |= ((uint32_t)s_nib[t * 8 + i]) << (4 * i);
        g_mask[(size_t)row * 32 + t] = w;
    }
}

// ---------------------------------------------------------------------------
// prep_x: transpose to fp16 xT[b][h][k], packed half2 stores
// tile: 64 k-rows x 32 h-cols per block (256 threads)
// ---------------------------------------------------------------------------
__global__ void prep_x_kernel(const float* __restrict__ x) {
    __shared__ float tile[64][33];
    const int b = blockIdx.z;
    const int k0 = blockIdx.y * 64;
    const int h0 = blockIdx.x * 32;
    const int t = threadIdx.x;
    const int wid = t >> 5, lane = t & 31;

#pragma unroll
    for (int i = 0; i < 8; ++i) {
        int r = wid + i * 8;
        tile[r][lane] = x[((size_t)(b * NN + k0 + r)) * HH + h0 + lane];
    }
    __syncthreads();

    uint32_t* xo = (uint32_t*)g_xT;
#pragma unroll
    for (int i = 0; i < 4; ++i) {
        const int h = h0 + wid + i * 8;
        const __half2 p = __floats2half2_rn(tile[2 * lane][wid + i * 8],
                                            tile[2 * lane + 1][wid + i * 8]);
        const size_t base = ((size_t)(b * HH + h)) * (NN / 2) + (k0 >> 1);
        xo[base + lane] = *(const uint32_t*)&p;
    }
}

// ---------------------------------------------------------------------------
// u1 = W @ a[:H], u2 = W @ a[H:]
// ---------------------------------------------------------------------------
__global__ void compute_u_kernel(const float* __restrict__ W, const float* __restrict__ a) {
    int g = blockIdx.x * blockDim.x + threadIdx.x;
    if (g >= HH) return;
    const float* wr = W + (size_t)g * HH;
    float u1 = 0.f, u2 = 0.f;
#pragma unroll 8
    for (int f = 0; f < HH; ++f) {
        float w = wr[f];
        u1 += w * a[f];
        u2 += w * a[HH + f];
    }
    g_u1[g] = u1;
    g_u2[g] = u2;
}

// ---------------------------------------------------------------------------
// v1[b,j] = x[b,j,:].u1 ; v2 = x.u2   (one warp per row, exact fp32)
// ---------------------------------------------------------------------------
__global__ void compute_v_kernel(const float* __restrict__ x) {
    const int row = blockIdx.x * 8 + (threadIdx.x >> 5);
    const int lane = threadIdx.x & 31;
    const float4* r = (const float4*)(x + (size_t)row * HH);
    const float4* u1 = (const float4*)g_u1;
    const float4* u2 = (const float4*)g_u2;
    float d1 = 0.f, d2 = 0.f;
#pragma unroll
    for (int k = lane; k < HH / 4; k += 32) {
        float4 v = r[k], w1 = u1[k], w2 = u2[k];
        d1 += v.x * w1.x + v.y * w1.y + v.z * w1.z + v.w * w1.w;
        d2 += v.x * w2.x + v.y * w2.y + v.z * w2.z + v.w * w2.w;
    }
#pragma unroll
    for (int o = 16; o > 0; o >>= 1) {
        d1 += __shfl_down_sync(0xffffffffu, d1, o);
        d2 += __shfl_down_sync(0xffffffffu, d2, o);
    }
    if (lane == 0) { g_v1[row] = d1; g_v2[row] = d2; }
}

// ---------------------------------------------------------------------------
// s1[b,i] = sum_{j in mask(i)} v1[b,j]   (exact fp32; lane l owns mask word l)
// block = (b, 128 rows); 8 warps x 16 row-iterations
// ---------------------------------------------------------------------------
__global__ void compute_s_kernel() {
    __shared__ float v1s[NN], v2s[NN];
    const int b = blockIdx.x >> 3;
    const int rg = blockIdx.x & 7;
    const int t = threadIdx.x;
    const int wid = t >> 5, lane = t & 31;

#pragma unroll
    for (int i = 0; i < 4; ++i) {
        v1s[t + i * 256] = g_v1[b * NN + t + i * 256];
        v2s[t + i * 256] = g_v2[b * NN + t + i * 256];
    }
    __syncthreads();

#pragma unroll 1
    for (int it = 0; it < 16; ++it) {
        const int ri = b * NN + rg * 128 + wid * 16 + it;
        uint32_t m = g_mask[(size_t)ri * 32 + lane];
        float s1 = 0.f, s2 = 0.f;
        while (m) {
            int bit = __ffs(m) - 1;
            m &= m - 1;
            s1 += v1s[lane * 32 + bit];
            s2 += v2s[lane * 32 + bit];
        }
#pragma unroll
        for (int o = 16; o > 0; o >>= 1) {
            s1 += __shfl_down_sync(0xffffffffu, s1, o);
            s2 += __shfl_down_sync(0xffffffffu, s2, o);
        }
        if (lane == 0) { g_s1[ri] = s1; g_s2[ri] = s2; }
    }
}

// ---------------------------------------------------------------------------
// GEMM fp16 single-pass: nv[b, i0:+128, h0:+128] = adj[b] @ x, K=1024
// CTA 128x128, KT=64, double-buffered cp.async, XOR-swizzled smem.
// ---------------------------------------------------------------------------
#define NKT 16
#define STAGE_B 32768          // A 16KB + B 16KB
#define GEMM_SMEM (2 * STAGE_B)

__device__ __forceinline__ void gemm_load(uint32_t sbase, int stage,
                                          const __half* gA, const __half* gB, int kt) {
    const int t = threadIdx.x;
    const uint32_t sA = sbase + (uint32_t)stage * STAGE_B;
    const uint32_t sB = sA + 16384u;
    const int k0 = kt * 64;
#pragma unroll
    for (int i = 0; i < 4; ++i) {
        int idx = t + i * 256;           // 0..1023
        int r = idx >> 3;                // row 0..127
        int c = idx & 7;                 // 16B chunk
        uint32_t soff = (uint32_t)(r * 128 + ((c ^ (r & 7)) * 16));
        cp_async16(sA + soff, gA + (size_t)r * NN + k0 + c * 8);
        cp_async16(sB + soff, gB + (size_t)r * NN + k0 + c * 8);
    }
    asm volatile("cp.async.commit_group;" ::: "memory");
}

__global__ void __launch_bounds__(256, 2) gemm_kernel(float* __restrict__ nv) {
    extern __shared__ __align__(1024) char dsm[];
    const uint32_t sbase = smem_u32(dsm);
    const int tid = threadIdx.x;
    const int wid = tid >> 5, lane = tid & 31;
    const int warp_m = wid & 3, warp_n = wid >> 2;
    const int i0 = blockIdx.x * 128, h0 = blockIdx.y * 128;
    const int b = blockIdx.z;

    const __half* gA0 = g_adjh + ((size_t)(b * NN + i0)) * NN;
    const __half* gB0 = g_xT + ((size_t)(b * HH + h0)) * NN;

    float acc[2][8][4];
#pragma unroll
    for (int mi = 0; mi < 2; ++mi)
#pragma unroll
        for (int nf = 0; nf < 8; ++nf)
#pragma unroll
            for (int q = 0; q < 4; ++q) acc[mi][nf][q] = 0.f;

    const int rA = warp_m * 32 + (lane & 15);
    const int cselA = lane >> 4;
    const int rB0 = warp_n * 64 + (lane & 7) + ((lane >> 4) << 3);
    const int cselB = (lane >> 3) & 1;

    gemm_load(sbase, 0, gA0, gB0, 0);

#pragma unroll 1
    for (int kt = 0; kt < NKT; ++kt) {
        if (kt + 1 < NKT) {
            gemm_load(sbase, (kt + 1) & 1, gA0, gB0, kt + 1);
            asm volatile("cp.async.wait_group 1;" ::: "memory");
        } else {
            asm volatile("cp.async.wait_group 0;" ::: "memory");
        }
        __syncthreads();

        const uint32_t sA = sbase + (uint32_t)(kt & 1) * STAGE_B;
        const uint32_t sB = sA + 16384u;
#pragma unroll
        for (int ks = 0; ks < 4; ++ks) {
            uint32_t a[2][4];
#pragma unroll
            for (int mi = 0; mi < 2; ++mi) {
                int row = rA + mi * 16;
                uint32_t ad = sA + (uint32_t)(row * 128 + (((ks * 2 + cselA) ^ (row & 7)) * 16));
                ldmx4(a[mi][0], a[mi][1], a[mi][2], a[mi][3], ad);
            }
            uint32_t bf[8][2];
#pragma unroll
            for (int nj = 0; nj < 4; ++nj) {
                int row = rB0 + nj * 16;
                uint32_t ad = sB + (uint32_t)(row * 128 + (((ks * 2 + cselB) ^ (row & 7)) * 16));
                uint32_t r0, r1, r2, r3;
                ldmx4(r0, r1, r2, r3, ad);
                bf[2 * nj][0] = r0; bf[2 * nj][1] = r1;
                bf[2 * nj + 1][0] = r2; bf[2 * nj + 1][1] = r3;
            }
#pragma unroll
            for (int mi = 0; mi < 2; ++mi)
#pragma unroll
                for (int nf = 0; nf < 8; ++nf)
                    mma16816(acc[mi][nf], a[mi], bf[nf]);
        }
        __syncthreads();
    }

    const int g = lane >> 2, t4 = lane & 3;
#pragma unroll
    for (int mi = 0; mi < 2; ++mi) {
#pragma unroll
        for (int nf = 0; nf < 8; ++nf) {
            int row0 = i0 + warp_m * 32 + mi * 16 + g;
            int col = h0 + warp_n * 64 + nf * 8 + t4 * 2;
            float* p0 = nv + ((size_t)(b * NN) + row0) * HH + col;
            *(float2*)p0 = make_float2(acc[mi][nf][0], acc[mi][nf][1]);
            *(float2*)(p0 + 8 * HH) = make_float2(acc[mi][nf][2], acc[mi][nf][3]);
        }
    }
}

// ---------------------------------------------------------------------------
// softmax: bitmask-driven, register-resident scores
// ---------------------------------------------------------------------------
__global__ void softmax_kernel(const float* __restrict__ nl, float* __restrict__ attn) {
    __shared__ float red[8];
    __shared__ float bc;
    const int row = blockIdx.x;
    const int b = row >> 10;
    const int tid = threadIdx.x;

    const float s1i = g_s1[row];
    const bool rv = nl[row] > 1e-6f;
    const uint32_t* mrow = g_mask + (size_t)row * 32;
    const float* nlb = nl + (size_t)b * NN;
    const float* s2b = g_s2 + (size_t)b * NN;

    float sc[4];
    float lmax = NEG_INF_F;
#pragma unroll
    for (int k = 0; k < 4; ++k) {
        const int j = tid + 256 * k;
        const uint32_t w = mrow[j >> 5];
        const bool v = (((w >> (j & 31)) & 1u) != 0u) && rv && (nlb[j] > 1e-6f);
        const float z = s1i + s2b[j];
        const float e = (z > 0.f) ? z : SLOPE_F * z;
        sc[k] = v ? e : NEG_INF_F;
        lmax = fmaxf(lmax, sc[k]);
    }
#pragma unroll
    for (int o = 16; o > 0; o >>= 1)
        lmax = fmaxf(lmax, __shfl_xor_sync(0xffffffffu, lmax, o));
    if ((tid & 31) == 0) red[tid >> 5] = lmax;
    __syncthreads();
    if (tid == 0) {
        float m = red[0];
#pragma unroll
        for (int k = 1; k < 8; ++k) m = fmaxf(m, red[k]);
        bc = m;
    }
    __syncthreads();
    const float m = bc;

    float lsum = 0.f;
#pragma unroll
    for (int k = 0; k < 4; ++k) {
        const float e = __expf(sc[k] - m);
        sc[k] = e;
        lsum += e;
    }
#pragma unroll
    for (int o = 16; o > 0; o >>= 1)
        lsum += __shfl_xor_sync(0xffffffffu, lsum, o);
    if ((tid & 31) == 0) red[tid >> 5] = lsum;
    __syncthreads();
    if (tid == 0) {
        float s = 0.f;
#pragma unroll
        for (int k = 0; k < 8; ++k) s += red[k];
        bc = 1.0f / s;
    }
    __syncthreads();
    const float inv = bc;

    float* orow = attn + (size_t)row * NN;
#pragma unroll
    for (int k = 0; k < 4; ++k)
        orow[tid + 256 * k] = sc[k] * inv;
}

// ---------------------------------------------------------------------------
extern "C" void kernel_launch(void* const* d_in, const int* in_sizes, int n_in,
                              void* d_out, int out_size) {
    const float* x   = (const float*)d_in[0];   // (B, N, H)
    const float* nl  = (const float*)d_in[1];   // (B, N)
    const float* adj = (const float*)d_in[2];   // (B, N, N)
    const float* W   = (const float*)d_in[3];   // (H, H)
    const float* a   = (const float*)d_in[4];   // (2H, 1)

    float* nv   = (float*)d_out;
    float* attn = nv + (size_t)BB * NN * HH;

    cudaFuncSetAttribute(gemm_kernel, cudaFuncAttributeMaxDynamicSharedMemorySize, GEMM_SMEM);

    prep_adj_kernel<<<BB * NN, 256>>>(adj);
    prep_x_kernel<<<dim3(HH / 32, NN / 64, BB), 256>>>(x);
    compute_u_kernel<<<3, 256>>>(W, a);
    compute_v_kernel<<<(BB * NN) / 8, 256>>>(x);
    compute_s_kernel<<<BB * 8, 256>>>();
    gemm_kernel<<<dim3(NN / 128, HH / 128, BB), 256, GEMM_SMEM>>>(nv);
    softmax_kernel<<<BB * NN, 256>>>(nl, attn);
}

// round 10
// speedup vs baseline: 1.9969x; 1.3972x over previous
#include <cuda_runtime.h>
#include <cuda_fp16.h>
#include <cstdint>

#define BB 16
#define NN 1024
#define HH 768
#define NEG_INF_F (-9000000000000000.0f)
#define SLOPE_F 0.2f

// ---- static device scratch (no allocations allowed) ----
__device__ __align__(16) __half g_adjh[(size_t)BB * NN * NN];   // adj fp16 (exact 0/1) 33.5 MB
__device__ __align__(16) __half g_xT[(size_t)BB * HH * NN];     // xT fp16 [b][h][k] 25 MB
__device__ uint32_t g_mask[(size_t)BB * NN * 32];               // 2 MB
__device__ __align__(16) float g_u1[HH], g_u2[HH];
__device__ float g_v1[BB * NN], g_v2[BB * NN];
__device__ float g_s1[BB * NN], g_s2[BB * NN];

__device__ __forceinline__ uint32_t smem_u32(const void* p) {
    uint32_t a;
    asm("{ .reg .u64 t; cvta.to.shared.u64 t, %1; cvt.u32.u64 %0, t; }" : "=r"(a) : "l"(p));
    return a;
}
__device__ __forceinline__ void cp_async16(uint32_t dst, const void* src) {
    asm volatile("cp.async.cg.shared.global [%0], [%1], 16;" :: "r"(dst), "l"(src) : "memory");
}
__device__ __forceinline__ void ldmx4(uint32_t& r0, uint32_t& r1, uint32_t& r2, uint32_t& r3, uint32_t a) {
    asm volatile("ldmatrix.sync.aligned.m8n8.x4.shared.b16 {%0,%1,%2,%3}, [%4];"
                 : "=r"(r0), "=r"(r1), "=r"(r2), "=r"(r3) : "r"(a));
}
__device__ __forceinline__ void mma16816(float* d, const uint32_t* a, const uint32_t* b) {
    asm volatile("mma.sync.aligned.m16n8k16.row.col.f32.f16.f16.f32 "
                 "{%0,%1,%2,%3}, {%4,%5,%6,%7}, {%8,%9}, {%0,%1,%2,%3};"
                 : "+f"(d[0]), "+f"(d[1]), "+f"(d[2]), "+f"(d[3])
                 : "r"(a[0]), "r"(a[1]), "r"(a[2]), "r"(a[3]), "r"(b[0]), "r"(b[1]));
}

// ---------------------------------------------------------------------------
// prep_adj: fp32 -> fp16 (exact 0/1) + validity bitmask
// ---------------------------------------------------------------------------
__global__ void prep_adj_kernel(const float* __restrict__ adj) {
    __shared__ unsigned char s_nib[256];
    const int row = blockIdx.x;
    const int t = threadIdx.x;
    const float4 v = ((const float4*)(adj + (size_t)row * NN))[t];
    __half2 p0 = __floats2half2_rn(v.x, v.y);
    __half2 p1 = __floats2half2_rn(v.z, v.w);
    uint2 u;
    u.x = *(const uint32_t*)&p0;
    u.y = *(const uint32_t*)&p1;
    ((uint2*)(g_adjh + (size_t)row * NN))[t] = u;
    unsigned nib = (v.x > 1e-6f ? 1u : 0u) | (v.y > 1e-6f ? 2u : 0u) |
                   (v.z > 1e-6f ? 4u : 0u) | (v.w > 1e-6f ? 8u : 0u);
    s_nib[t] = (unsigned char)nib;
    __syncthreads();
    if (t < 32) {
        uint32_t w = 0;
#pragma unroll
        for (int i = 0; i < 8; ++i) w |= ((uint32_t)s_nib[t * 8 + i]) << (4 * i);
        g_mask[(size_t)row * 32 + t] = w;
    }
}

// ---------------------------------------------------------------------------
// prep_x: transpose to fp16 xT[b][h][k], packed half2 stores
// ---------------------------------------------------------------------------
__global__ void prep_x_kernel(const float* __restrict__ x) {
    __shared__ float tile[64][33];
    const int b = blockIdx.z;
    const int k0 = blockIdx.y * 64;
    const int h0 = blockIdx.x * 32;
    const int t = threadIdx.x;
    const int wid = t >> 5, lane = t & 31;

#pragma unroll
    for (int i = 0; i < 8; ++i) {
        int r = wid + i * 8;
        tile[r][lane] = x[((size_t)(b * NN + k0 + r)) * HH + h0 + lane];
    }
    __syncthreads();

    uint32_t* xo = (uint32_t*)g_xT;
#pragma unroll
    for (int i = 0; i < 4; ++i) {
        const int h = h0 + wid + i * 8;
        const __half2 p = __floats2half2_rn(tile[2 * lane][wid + i * 8],
                                            tile[2 * lane + 1][wid + i * 8]);
        const size_t base = ((size_t)(b * HH + h)) * (NN / 2) + (k0 >> 1);
        xo[base + lane] = *(const uint32_t*)&p;
    }
}

// ---------------------------------------------------------------------------
// u1 = W @ a[:H], u2 = W @ a[H:]
// ---------------------------------------------------------------------------
__global__ void compute_u_kernel(const float* __restrict__ W, const float* __restrict__ a) {
    int g = blockIdx.x * blockDim.x + threadIdx.x;
    if (g >= HH) return;
    const float* wr = W + (size_t)g * HH;
    float u1 = 0.f, u2 = 0.f;
#pragma unroll 8
    for (int f = 0; f < HH; ++f) {
        float w = wr[f];
        u1 += w * a[f];
        u2 += w * a[HH + f];
    }
    g_u1[g] = u1;
    g_u2[g] = u2;
}

// ---------------------------------------------------------------------------
// v1[b,j] = x[b,j,:].u1 ; v2 = x.u2   (one warp per row, exact fp32)
// ---------------------------------------------------------------------------
__global__ void compute_v_kernel(const float* __restrict__ x) {
    const int row = blockIdx.x * 8 + (threadIdx.x >> 5);
    const int lane = threadIdx.x & 31;
    const float4* r = (const float4*)(x + (size_t)row * HH);
    const float4* u1 = (const float4*)g_u1;
    const float4* u2 = (const float4*)g_u2;
    float d1 = 0.f, d2 = 0.f;
#pragma unroll
    for (int k = lane; k < HH / 4; k += 32) {
        float4 v = r[k], w1 = u1[k], w2 = u2[k];
        d1 += v.x * w1.x + v.y * w1.y + v.z * w1.z + v.w * w1.w;
        d2 += v.x * w2.x + v.y * w2.y + v.z * w2.z + v.w * w2.w;
    }
#pragma unroll
    for (int o = 16; o > 0; o >>= 1) {
        d1 += __shfl_down_sync(0xffffffffu, d1, o);
        d2 += __shfl_down_sync(0xffffffffu, d2, o);
    }
    if (lane == 0) { g_v1[row] = d1; g_v2[row] = d2; }
}

// ---------------------------------------------------------------------------
// s1[b,i] = sum_{j in mask(i)} v1[b,j]   (exact fp32)
// ---------------------------------------------------------------------------
__global__ void compute_s_kernel() {
    __shared__ float v1s[NN], v2s[NN];
    const int b = blockIdx.x >> 3;
    const int rg = blockIdx.x & 7;
    const int t = threadIdx.x;
    const int wid = t >> 5, lane = t & 31;

#pragma unroll
    for (int i = 0; i < 4; ++i) {
        v1s[t + i * 256] = g_v1[b * NN + t + i * 256];
        v2s[t + i * 256] = g_v2[b * NN + t + i * 256];
    }
    __syncthreads();

#pragma unroll 1
    for (int it = 0; it < 16; ++it) {
        const int ri = b * NN + rg * 128 + wid * 16 + it;
        uint32_t m = g_mask[(size_t)ri * 32 + lane];
        float s1 = 0.f, s2 = 0.f;
        while (m) {
            int bit = __ffs(m) - 1;
            m &= m - 1;
            s1 += v1s[lane * 32 + bit];
            s2 += v2s[lane * 32 + bit];
        }
#pragma unroll
        for (int o = 16; o > 0; o >>= 1) {
            s1 += __shfl_down_sync(0xffffffffu, s1, o);
            s2 += __shfl_down_sync(0xffffffffu, s2, o);
        }
        if (lane == 0) { g_s1[ri] = s1; g_s2[ri] = s2; }
    }
}

// ---------------------------------------------------------------------------
// GEMM fp16 single-pass: nv[b, i0:+128, h0:+128] = adj[b] @ x, K=1024
// ---------------------------------------------------------------------------
#define NKT 16
#define STAGE_B 32768          // A 16KB + B 16KB
#define GEMM_SMEM (2 * STAGE_B)

__device__ __forceinline__ void gemm_load(uint32_t sbase, int stage,
                                          const __half* gA, const __half* gB, int kt) {
    const int t = threadIdx.x;
    const uint32_t sA = sbase + (uint32_t)stage * STAGE_B;
    const uint32_t sB = sA + 16384u;
    const int k0 = kt * 64;
#pragma unroll
    for (int i = 0; i < 4; ++i) {
        int idx = t + i * 256;           // 0..1023
        int r = idx >> 3;                // row 0..127
        int c = idx & 7;                 // 16B chunk
        uint32_t soff = (uint32_t)(r * 128 + ((c ^ (r & 7)) * 16));
        cp_async16(sA + soff, gA + (size_t)r * NN + k0 + c * 8);
        cp_async16(sB + soff, gB + (size_t)r * NN + k0 + c * 8);
    }
    asm volatile("cp.async.commit_group;" ::: "memory");
}

__global__ void __launch_bounds__(256, 2) gemm_kernel(float* __restrict__ nv) {
    extern __shared__ __align__(1024) char dsm[];
    const uint32_t sbase = smem_u32(dsm);
    const int tid = threadIdx.x;
    const int wid = tid >> 5, lane = tid & 31;
    const int warp_m = wid & 3, warp_n = wid >> 2;
    const int i0 = blockIdx.x * 128, h0 = blockIdx.y * 128;
    const int b = blockIdx.z;

    const __half* gA0 = g_adjh + ((size_t)(b * NN + i0)) * NN;
    const __half* gB0 = g_xT + ((size_t)(b * HH + h0)) * NN;

    float acc[2][8][4];
#pragma unroll
    for (int mi = 0; mi < 2; ++mi)
#pragma unroll
        for (int nf = 0; nf < 8; ++nf)
#pragma unroll
            for (int q = 0; q < 4; ++q) acc[mi][nf][q] = 0.f;

    const int rA = warp_m * 32 + (lane & 15);
    const int cselA = lane >> 4;
    const int rB0 = warp_n * 64 + (lane & 7) + ((lane >> 4) << 3);
    const int cselB = (lane >> 3) & 1;

    gemm_load(sbase, 0, gA0, gB0, 0);

#pragma unroll 1
    for (int kt = 0; kt < NKT; ++kt) {
        if (kt + 1 < NKT) {
            gemm_load(sbase, (kt + 1) & 1, gA0, gB0, kt + 1);
            asm volatile("cp.async.wait_group 1;" ::: "memory");
        } else {
            asm volatile("cp.async.wait_group 0;" ::: "memory");
        }
        __syncthreads();

        const uint32_t sA = sbase + (uint32_t)(kt & 1) * STAGE_B;
        const uint32_t sB = sA + 16384u;
#pragma unroll
        for (int ks = 0; ks < 4; ++ks) {
            uint32_t a[2][4];
#pragma unroll
            for (int mi = 0; mi < 2; ++mi) {
                int row = rA + mi * 16;
                uint32_t ad = sA + (uint32_t)(row * 128 + (((ks * 2 + cselA) ^ (row & 7)) * 16));
                ldmx4(a[mi][0], a[mi][1], a[mi][2], a[mi][3], ad);
            }
            uint32_t bf[8][2];
#pragma unroll
            for (int nj = 0; nj < 4; ++nj) {
                int row = rB0 + nj * 16;
                uint32_t ad = sB + (uint32_t)(row * 128 + (((ks * 2 + cselB) ^ (row & 7)) * 16));
                uint32_t r0, r1, r2, r3;
                ldmx4(r0, r1, r2, r3, ad);
                bf[2 * nj][0] = r0; bf[2 * nj][1] = r1;
                bf[2 * nj + 1][0] = r2; bf[2 * nj + 1][1] = r3;
            }
#pragma unroll
            for (int mi = 0; mi < 2; ++mi)
#pragma unroll
                for (int nf = 0; nf < 8; ++nf)
                    mma16816(acc[mi][nf], a[mi], bf[nf]);
        }
        __syncthreads();
    }

    const int g = lane >> 2, t4 = lane & 3;
#pragma unroll
    for (int mi = 0; mi < 2; ++mi) {
#pragma unroll
        for (int nf = 0; nf < 8; ++nf) {
            int row0 = i0 + warp_m * 32 + mi * 16 + g;
            int col = h0 + warp_n * 64 + nf * 8 + t4 * 2;
            float* p0 = nv + ((size_t)(b * NN) + row0) * HH + col;
            *(float2*)p0 = make_float2(acc[mi][nf][0], acc[mi][nf][1]);
            *(float2*)(p0 + 8 * HH) = make_float2(acc[mi][nf][2], acc[mi][nf][3]);
        }
    }
}

// ---------------------------------------------------------------------------
// softmax: bitmask-driven, register-resident scores
// ---------------------------------------------------------------------------
__global__ void softmax_kernel(const float* __restrict__ nl, float* __restrict__ attn) {
    __shared__ float red[8];
    __shared__ float bc;
    const int row = blockIdx.x;
    const int b = row >> 10;
    const int tid = threadIdx.x;

    const float s1i = g_s1[row];
    const bool rv = nl[row] > 1e-6f;
    const uint32_t* mrow = g_mask + (size_t)row * 32;
    const float* nlb = nl + (size_t)b * NN;
    const float* s2b = g_s2 + (size_t)b * NN;

    float sc[4];
    float lmax = NEG_INF_F;
#pragma unroll
    for (int k = 0; k < 4; ++k) {
        const int j = tid + 256 * k;
        const uint32_t w = mrow[j >> 5];
        const bool v = (((w >> (j & 31)) & 1u) != 0u) && rv && (nlb[j] > 1e-6f);
        const float z = s1i + s2b[j];
        const float e = (z > 0.f) ? z : SLOPE_F * z;
        sc[k] = v ? e : NEG_INF_F;
        lmax = fmaxf(lmax, sc[k]);
    }
#pragma unroll
    for (int o = 16; o > 0; o >>= 1)
        lmax = fmaxf(lmax, __shfl_xor_sync(0xffffffffu, lmax, o));
    if ((tid & 31) == 0) red[tid >> 5] = lmax;
    __syncthreads();
    if (tid == 0) {
        float m = red[0];
#pragma unroll
        for (int k = 1; k < 8; ++k) m = fmaxf(m, red[k]);
        bc = m;
    }
    __syncthreads();
    const float m = bc;

    float lsum = 0.f;
#pragma unroll
    for (int k = 0; k < 4; ++k) {
        const float e = __expf(sc[k] - m);
        sc[k] = e;
        lsum += e;
    }
#pragma unroll
    for (int o = 16; o > 0; o >>= 1)
        lsum += __shfl_xor_sync(0xffffffffu, lsum, o);
    if ((tid & 31) == 0) red[tid >> 5] = lsum;
    __syncthreads();
    if (tid == 0) {
        float s = 0.f;
#pragma unroll
        for (int k = 0; k < 8; ++k) s += red[k];
        bc = 1.0f / s;
    }
    __syncthreads();
    const float inv = bc;

    float* orow = attn + (size_t)row * NN;
#pragma unroll
    for (int k = 0; k < 4; ++k)
        orow[tid + 256 * k] = sc[k] * inv;
}

// ---------------------------------------------------------------------------
// launch: two-stream overlap (chain A: prep_adj->prep_x->gemm on capture
// stream; chain B: u->v->[mask]->s->softmax on side stream), event fork/join.
// ---------------------------------------------------------------------------
extern "C" void kernel_launch(void* const* d_in, const int* in_sizes, int n_in,
                              void* d_out, int out_size) {
    const float* x   = (const float*)d_in[0];   // (B, N, H)
    const float* nl  = (const float*)d_in[1];   // (B, N)
    const float* adj = (const float*)d_in[2];   // (B, N, N)
    const float* W   = (const float*)d_in[3];   // (H, H)
    const float* a   = (const float*)d_in[4];   // (2H, 1)

    float* nv   = (float*)d_out;
    float* attn = nv + (size_t)BB * NN * HH;

    static cudaStream_t s2 = nullptr;
    static cudaEvent_t ev0 = nullptr, evA = nullptr, evB = nullptr;
    static int inited = 0;
    if (!inited) {
        cudaFuncSetAttribute(gemm_kernel, cudaFuncAttributeMaxDynamicSharedMemorySize, GEMM_SMEM);
        cudaStreamCreateWithFlags(&s2, cudaStreamNonBlocking);
        cudaEventCreateWithFlags(&ev0, cudaEventDisableTiming);
        cudaEventCreateWithFlags(&evA, cudaEventDisableTiming);
        cudaEventCreateWithFlags(&evB, cudaEventDisableTiming);
        inited = 1;
    }

    // fork side stream off the capture (default) stream
    cudaEventRecord(ev0, 0);
    cudaStreamWaitEvent(s2, ev0, 0);

    // chain A on default stream
    prep_adj_kernel<<<BB * NN, 256>>>(adj);
    cudaEventRecord(evA, 0);                    // mask ready
    prep_x_kernel<<<dim3(HH / 32, NN / 64, BB), 256>>>(x);
    gemm_kernel<<<dim3(NN / 128, HH / 128, BB), 256, GEMM_SMEM>>>(nv);

    // chain B on side stream
    compute_u_kernel<<<3, 256, 0, s2>>>(W, a);
    compute_v_kernel<<<(BB * NN) / 8, 256, 0, s2>>>(x);
    cudaStreamWaitEvent(s2, evA, 0);            // need g_mask
    compute_s_kernel<<<BB * 8, 256, 0, s2>>>();
    softmax_kernel<<<BB * NN, 256, 0, s2>>>(nl, attn);
    cudaEventRecord(evB, s2);

    // join
    cudaStreamWaitEvent(0, evB, 0);
}

// round 11
// speedup vs baseline: 2.7669x; 1.3856x over previous
#include <cuda_runtime.h>
#include <cuda_fp16.h>
#include <cstdint>

#define BB 16
#define NN 1024
#define HH 768
#define NEG_INF_F (-9000000000000000.0f)
#define SLOPE_F 0.2f

// ---- static device scratch (no allocations allowed) ----
__device__ __align__(16) __half g_adjh[(size_t)BB * NN * NN];   // adj fp16 (exact 0/1) 33.5 MB
__device__ __align__(16) __half g_xT[(size_t)BB * HH * NN];     // xT fp16 [b][h][k] 25 MB
__device__ uint32_t g_mask[(size_t)BB * NN * 32];               // 2 MB
__device__ __align__(16) float g_u1[HH], g_u2[HH];
__device__ float g_v1[BB * NN], g_v2[BB * NN];
__device__ float g_s1[BB * NN], g_s2[BB * NN];

__device__ __forceinline__ uint32_t smem_u32(const void* p) {
    uint32_t a;
    asm("{ .reg .u64 t; cvta.to.shared.u64 t, %1; cvt.u32.u64 %0, t; }" : "=r"(a) : "l"(p));
    return a;
}
__device__ __forceinline__ void cp_async16(uint32_t dst, const void* src) {
    asm volatile("cp.async.cg.shared.global [%0], [%1], 16;" :: "r"(dst), "l"(src) : "memory");
}
__device__ __forceinline__ void ldmx4(uint32_t& r0, uint32_t& r1, uint32_t& r2, uint32_t& r3, uint32_t a) {
    asm volatile("ldmatrix.sync.aligned.m8n8.x4.shared.b16 {%0,%1,%2,%3}, [%4];"
                 : "=r"(r0), "=r"(r1), "=r"(r2), "=r"(r3) : "r"(a));
}
__device__ __forceinline__ void mma16816(float* d, const uint32_t* a, const uint32_t* b) {
    asm volatile("mma.sync.aligned.m16n8k16.row.col.f32.f16.f16.f32 "
                 "{%0,%1,%2,%3}, {%4,%5,%6,%7}, {%8,%9}, {%0,%1,%2,%3};"
                 : "+f"(d[0]), "+f"(d[1]), "+f"(d[2]), "+f"(d[3])
                 : "r"(a[0]), "r"(a[1]), "r"(a[2]), "r"(a[3]), "r"(b[0]), "r"(b[1]));
}

// ---------------------------------------------------------------------------
// prep_adj: fp32 -> fp16 (exact 0/1) + validity bitmask
// ---------------------------------------------------------------------------
__global__ void prep_adj_kernel(const float* __restrict__ adj) {
    __shared__ unsigned char s_nib[256];
    const int row = blockIdx.x;
    const int t = threadIdx.x;
    const float4 v = ((const float4*)(adj + (size_t)row * NN))[t];
    __half2 p0 = __floats2half2_rn(v.x, v.y);
    __half2 p1 = __floats2half2_rn(v.z, v.w);
    uint2 u;
    u.x = *(const uint32_t*)&p0;
    u.y = *(const uint32_t*)&p1;
    ((uint2*)(g_adjh + (size_t)row * NN))[t] = u;
    unsigned nib = (v.x > 1e-6f ? 1u : 0u) | (v.y > 1e-6f ? 2u : 0u) |
                   (v.z > 1e-6f ? 4u : 0u) | (v.w > 1e-6f ? 8u : 0u);
    s_nib[t] = (unsigned char)nib;
    __syncthreads();
    if (t < 32) {
        uint32_t w = 0;
#pragma unroll
        for (int i = 0; i < 8; ++i) w |= ((uint32_t)s_nib[t * 8 + i]) << (4 * i);
        g_mask[(size_t)row * 32 + t] = w;
    }
}

// ---------------------------------------------------------------------------
// prep_x: transpose to fp16 xT[b][h][k], packed half2 stores
// ---------------------------------------------------------------------------
__global__ void prep_x_kernel(const float* __restrict__ x) {
    __shared__ float tile[64][33];
    const int b = blockIdx.z;
    const int k0 = blockIdx.y * 64;
    const int h0 = blockIdx.x * 32;
    const int t = threadIdx.x;
    const int wid = t >> 5, lane = t & 31;

#pragma unroll
    for (int i = 0; i < 8; ++i) {
        int r = wid + i * 8;
        tile[r][lane] = x[((size_t)(b * NN + k0 + r)) * HH + h0 + lane];
    }
    __syncthreads();

    uint32_t* xo = (uint32_t*)g_xT;
#pragma unroll
    for (int i = 0; i < 4; ++i) {
        const int h = h0 + wid + i * 8;
        const __half2 p = __floats2half2_rn(tile[2 * lane][wid + i * 8],
                                            tile[2 * lane + 1][wid + i * 8]);
        const size_t base = ((size_t)(b * HH + h)) * (NN / 2) + (k0 >> 1);
        xo[base + lane] = *(const uint32_t*)&p;
    }
}

// ---------------------------------------------------------------------------
// u1 = W @ a[:H], u2 = W @ a[H:]  — one warp per output element (768 warps)
// ---------------------------------------------------------------------------
__global__ void compute_u_kernel(const float* __restrict__ W, const float* __restrict__ a) {
    const int g = blockIdx.x * 8 + (threadIdx.x >> 5);
    const int lane = threadIdx.x & 31;
    const float* wr = W + (size_t)g * HH;
    float u1 = 0.f, u2 = 0.f;
#pragma unroll
    for (int f = lane; f < HH; f += 32) {
        const float w = wr[f];
        u1 += w * a[f];
        u2 += w * a[HH + f];
    }
#pragma unroll
    for (int o = 16; o > 0; o >>= 1) {
        u1 += __shfl_down_sync(0xffffffffu, u1, o);
        u2 += __shfl_down_sync(0xffffffffu, u2, o);
    }
    if (lane == 0) { g_u1[g] = u1; g_u2[g] = u2; }
}

// ---------------------------------------------------------------------------
// v1[b,j] = x[b,j,:].u1 ; v2 = x.u2   (one warp per row, exact fp32)
// ---------------------------------------------------------------------------
__global__ void compute_v_kernel(const float* __restrict__ x) {
    const int row = blockIdx.x * 8 + (threadIdx.x >> 5);
    const int lane = threadIdx.x & 31;
    const float4* r = (const float4*)(x + (size_t)row * HH);
    const float4* u1 = (const float4*)g_u1;
    const float4* u2 = (const float4*)g_u2;
    float d1 = 0.f, d2 = 0.f;
#pragma unroll
    for (int k = lane; k < HH / 4; k += 32) {
        float4 v = r[k], w1 = u1[k], w2 = u2[k];
        d1 += v.x * w1.x + v.y * w1.y + v.z * w1.z + v.w * w1.w;
        d2 += v.x * w2.x + v.y * w2.y + v.z * w2.z + v.w * w2.w;
    }
#pragma unroll
    for (int o = 16; o > 0; o >>= 1) {
        d1 += __shfl_down_sync(0xffffffffu, d1, o);
        d2 += __shfl_down_sync(0xffffffffu, d2, o);
    }
    if (lane == 0) { g_v1[row] = d1; g_v2[row] = d2; }
}

// ---------------------------------------------------------------------------
// s1[b,i] = sum_{j in mask(i)} v1[b,j]   (exact fp32)
// ---------------------------------------------------------------------------
__global__ void compute_s_kernel() {
    __shared__ float v1s[NN], v2s[NN];
    const int b = blockIdx.x >> 3;
    const int rg = blockIdx.x & 7;
    const int t = threadIdx.x;
    const int wid = t >> 5, lane = t & 31;

#pragma unroll
    for (int i = 0; i < 4; ++i) {
        v1s[t + i * 256] = g_v1[b * NN + t + i * 256];
        v2s[t + i * 256] = g_v2[b * NN + t + i * 256];
    }
    __syncthreads();

#pragma unroll 1
    for (int it = 0; it < 16; ++it) {
        const int ri = b * NN + rg * 128 + wid * 16 + it;
        uint32_t m = g_mask[(size_t)ri * 32 + lane];
        float s1 = 0.f, s2 = 0.f;
        while (m) {
            int bit = __ffs(m) - 1;
            m &= m - 1;
            s1 += v1s[lane * 32 + bit];
            s2 += v2s[lane * 32 + bit];
        }
#pragma unroll
        for (int o = 16; o > 0; o >>= 1) {
            s1 += __shfl_down_sync(0xffffffffu, s1, o);
            s2 += __shfl_down_sync(0xffffffffu, s2, o);
        }
        if (lane == 0) { g_s1[ri] = s1; g_s2[ri] = s2; }
    }
}

// ---------------------------------------------------------------------------
// GEMM fp16 single-pass: nv[b, i0:+128, h0:+128] = adj[b] @ x, K=1024
// ---------------------------------------------------------------------------
#define NKT 16
#define STAGE_B 32768          // A 16KB + B 16KB
#define GEMM_SMEM (2 * STAGE_B)

__device__ __forceinline__ void gemm_load(uint32_t sbase, int stage,
                                          const __half* gA, const __half* gB, int kt) {
    const int t = threadIdx.x;
    const uint32_t sA = sbase + (uint32_t)stage * STAGE_B;
    const uint32_t sB = sA + 16384u;
    const int k0 = kt * 64;
#pragma unroll
    for (int i = 0; i < 4; ++i) {
        int idx = t + i * 256;           // 0..1023
        int r = idx >> 3;                // row 0..127
        int c = idx & 7;                 // 16B chunk
        uint32_t soff = (uint32_t)(r * 128 + ((c ^ (r & 7)) * 16));
        cp_async16(sA + soff, gA + (size_t)r * NN + k0 + c * 8);
        cp_async16(sB + soff, gB + (size_t)r * NN + k0 + c * 8);
    }
    asm volatile("cp.async.commit_group;" ::: "memory");
}

__global__ void __launch_bounds__(256, 2) gemm_kernel(float* __restrict__ nv) {
    extern __shared__ __align__(1024) char dsm[];
    const uint32_t sbase = smem_u32(dsm);
    const int tid = threadIdx.x;
    const int wid = tid >> 5, lane = tid & 31;
    const int warp_m = wid & 3, warp_n = wid >> 2;
    const int i0 = blockIdx.x * 128, h0 = blockIdx.y * 128;
    const int b = blockIdx.z;

    const __half* gA0 = g_adjh + ((size_t)(b * NN + i0)) * NN;
    const __half* gB0 = g_xT + ((size_t)(b * HH + h0)) * NN;

    float acc[2][8][4];
#pragma unroll
    for (int mi = 0; mi < 2; ++mi)
#pragma unroll
        for (int nf = 0; nf < 8; ++nf)
#pragma unroll
            for (int q = 0; q < 4; ++q) acc[mi][nf][q] = 0.f;

    const int rA = warp_m * 32 + (lane & 15);
    const int cselA = lane >> 4;
    const int rB0 = warp_n * 64 + (lane & 7) + ((lane >> 4) << 3);
    const int cselB = (lane >> 3) & 1;

    gemm_load(sbase, 0, gA0, gB0, 0);

#pragma unroll 1
    for (int kt = 0; kt < NKT; ++kt) {
        if (kt + 1 < NKT) {
            gemm_load(sbase, (kt + 1) & 1, gA0, gB0, kt + 1);
            asm volatile("cp.async.wait_group 1;" ::: "memory");
        } else {
            asm volatile("cp.async.wait_group 0;" ::: "memory");
        }
        __syncthreads();

        const uint32_t sA = sbase + (uint32_t)(kt & 1) * STAGE_B;
        const uint32_t sB = sA + 16384u;
#pragma unroll
        for (int ks = 0; ks < 4; ++ks) {
            uint32_t a[2][4];
#pragma unroll
            for (int mi = 0; mi < 2; ++mi) {
                int row = rA + mi * 16;
                uint32_t ad = sA + (uint32_t)(row * 128 + (((ks * 2 + cselA) ^ (row & 7)) * 16));
                ldmx4(a[mi][0], a[mi][1], a[mi][2], a[mi][3], ad);
            }
            uint32_t bf[8][2];
#pragma unroll
            for (int nj = 0; nj < 4; ++nj) {
                int row = rB0 + nj * 16;
                uint32_t ad = sB + (uint32_t)(row * 128 + (((ks * 2 + cselB) ^ (row & 7)) * 16));
                uint32_t r0, r1, r2, r3;
                ldmx4(r0, r1, r2, r3, ad);
                bf[2 * nj][0] = r0; bf[2 * nj][1] = r1;
                bf[2 * nj + 1][0] = r2; bf[2 * nj + 1][1] = r3;
            }
#pragma unroll
            for (int mi = 0; mi < 2; ++mi)
#pragma unroll
                for (int nf = 0; nf < 8; ++nf)
                    mma16816(acc[mi][nf], a[mi], bf[nf]);
        }
        __syncthreads();
    }

    const int g = lane >> 2, t4 = lane & 3;
#pragma unroll
    for (int mi = 0; mi < 2; ++mi) {
#pragma unroll
        for (int nf = 0; nf < 8; ++nf) {
            int row0 = i0 + warp_m * 32 + mi * 16 + g;
            int col = h0 + warp_n * 64 + nf * 8 + t4 * 2;
            float* p0 = nv + ((size_t)(b * NN) + row0) * HH + col;
            *(float2*)p0 = make_float2(acc[mi][nf][0], acc[mi][nf][1]);
            *(float2*)(p0 + 8 * HH) = make_float2(acc[mi][nf][2], acc[mi][nf][3]);
        }
    }
}

// ---------------------------------------------------------------------------
// softmax: bitmask-driven, register-resident scores
// ---------------------------------------------------------------------------
__global__ void softmax_kernel(const float* __restrict__ nl, float* __restrict__ attn) {
    __shared__ float red[8];
    __shared__ float bc;
    const int row = blockIdx.x;
    const int b = row >> 10;
    const int tid = threadIdx.x;

    const float s1i = g_s1[row];
    const bool rv = nl[row] > 1e-6f;
    const uint32_t* mrow = g_mask + (size_t)row * 32;
    const float* nlb = nl + (size_t)b * NN;
    const float* s2b = g_s2 + (size_t)b * NN;

    float sc[4];
    float lmax = NEG_INF_F;
#pragma unroll
    for (int k = 0; k < 4; ++k) {
        const int j = tid + 256 * k;
        const uint32_t w = mrow[j >> 5];
        const bool v = (((w >> (j & 31)) & 1u) != 0u) && rv && (nlb[j] > 1e-6f);
        const float z = s1i + s2b[j];
        const float e = (z > 0.f) ? z : SLOPE_F * z;
        sc[k] = v ? e : NEG_INF_F;
        lmax = fmaxf(lmax, sc[k]);
    }
#pragma unroll
    for (int o = 16; o > 0; o >>= 1)
        lmax = fmaxf(lmax, __shfl_xor_sync(0xffffffffu, lmax, o));
    if ((tid & 31) == 0) red[tid >> 5] = lmax;
    __syncthreads();
    if (tid == 0) {
        float m = red[0];
#pragma unroll
        for (int k = 1; k < 8; ++k) m = fmaxf(m, red[k]);
        bc = m;
    }
    __syncthreads();
    const float m = bc;

    float lsum = 0.f;
#pragma unroll
    for (int k = 0; k < 4; ++k) {
        const float e = __expf(sc[k] - m);
        sc[k] = e;
        lsum += e;
    }
#pragma unroll
    for (int o = 16; o > 0; o >>= 1)
        lsum += __shfl_xor_sync(0xffffffffu, lsum, o);
    if ((tid & 31) == 0) red[tid >> 5] = lsum;
    __syncthreads();
    if (tid == 0) {
        float s = 0.f;
#pragma unroll
        for (int k = 0; k < 8; ++k) s += red[k];
        bc = 1.0f / s;
    }
    __syncthreads();
    const float inv = bc;

    float* orow = attn + (size_t)row * NN;
#pragma unroll
    for (int k = 0; k < 4; ++k)
        orow[tid + 256 * k] = sc[k] * inv;
}

// ---------------------------------------------------------------------------
// launch: two-stream overlap (chain A: prep_adj->prep_x->gemm on capture
// stream; chain B: u->v->[mask]->s->softmax on side stream), event fork/join.
// ---------------------------------------------------------------------------
extern "C" void kernel_launch(void* const* d_in, const int* in_sizes, int n_in,
                              void* d_out, int out_size) {
    const float* x   = (const float*)d_in[0];   // (B, N, H)
    const float* nl  = (const float*)d_in[1];   // (B, N)
    const float* adj = (const float*)d_in[2];   // (B, N, N)
    const float* W   = (const float*)d_in[3];   // (H, H)
    const float* a   = (const float*)d_in[4];   // (2H, 1)

    float* nv   = (float*)d_out;
    float* attn = nv + (size_t)BB * NN * HH;

    static cudaStream_t s2 = nullptr;
    static cudaEvent_t ev0 = nullptr, evA = nullptr, evB = nullptr;
    static int inited = 0;
    if (!inited) {
        cudaFuncSetAttribute(gemm_kernel, cudaFuncAttributeMaxDynamicSharedMemorySize, GEMM_SMEM);
        cudaStreamCreateWithFlags(&s2, cudaStreamNonBlocking);
        cudaEventCreateWithFlags(&ev0, cudaEventDisableTiming);
        cudaEventCreateWithFlags(&evA, cudaEventDisableTiming);
        cudaEventCreateWithFlags(&evB, cudaEventDisableTiming);
        inited = 1;
    }

    // fork side stream off the capture (default) stream
    cudaEventRecord(ev0, 0);
    cudaStreamWaitEvent(s2, ev0, 0);

    // chain A on default stream
    prep_adj_kernel<<<BB * NN, 256>>>(adj);
    cudaEventRecord(evA, 0);                    // mask ready
    prep_x_kernel<<<dim3(HH / 32, NN / 64, BB), 256>>>(x);
    gemm_kernel<<<dim3(NN / 128, HH / 128, BB), 256, GEMM_SMEM>>>(nv);

    // chain B on side stream
    compute_u_kernel<<<96, 256, 0, s2>>>(W, a);
    compute_v_kernel<<<(BB * NN) / 8, 256, 0, s2>>>(x);
    cudaStreamWaitEvent(s2, evA, 0);            // need g_mask
    compute_s_kernel<<<BB * 8, 256, 0, s2>>>();
    softmax_kernel<<<BB * NN, 256, 0, s2>>>(nl, attn);
    cudaEventRecord(evB, s2);

    // join
    cudaStreamWaitEvent(0, evB, 0);
}